// round 1
// baseline (speedup 1.0000x reference)
#include <cuda_runtime.h>
#include <math.h>

// ---------------------------------------------------------------------------
// Precomputed effective weights (device globals; rebuilt every launch)
// ---------------------------------------------------------------------------
__device__ float g_Weff0_ecc[25 * 64];
__device__ float g_Weff1_ecc[25 * 64];
__device__ float g_c0_ecc[64];
__device__ float g_Weff0_err[25 * 64];
__device__ float g_Weff1_err[25 * 64];
__device__ float g_c0_err[64];

__device__ float g_R_ecc[400 * 256];   // [V_ECC*25, 256]
__device__ float g_R_err[300 * 256];   // [V_ERR*25, 256]
__device__ float g_bias_ecc[256];
__device__ float g_bias_err[256];

// ---------------------------------------------------------------------------
// P1: fold temporal Conv1d (k=3, SAME, cross-correlation) into ChebConv W0/W1.
//   Weff[t'][g] = sum_{c,k} wt[c,k] * W[(c*25 + (t'-k+1))*64 + g]   (valid t)
//   c0[g]      = sum_c bt[c] * (colsum_t W0 - colsum_t W1) + b[g]
//   (uses L_hat row-sum == -1 for the bidirectional ring graph)
// ---------------------------------------------------------------------------
__global__ void precompute_weff(
    const float* __restrict__ wt_ecc, const float* __restrict__ bt_ecc,
    const float* __restrict__ wt_err, const float* __restrict__ bt_err,
    const float* __restrict__ W0_ecc, const float* __restrict__ W1_ecc,
    const float* __restrict__ b_ecc,
    const float* __restrict__ W0_err, const float* __restrict__ W1_err,
    const float* __restrict__ b_err)
{
    const int graph = blockIdx.x;  // 0 = ecc, 1 = err
    const float* wt = graph ? wt_err : wt_ecc;
    const float* bt = graph ? bt_err : bt_ecc;
    const float* W0 = graph ? W0_err : W0_ecc;
    const float* W1 = graph ? W1_err : W1_ecc;
    const float* bb = graph ? b_err  : b_ecc;
    float* Weff0 = graph ? g_Weff0_err : g_Weff0_ecc;
    float* Weff1 = graph ? g_Weff1_err : g_Weff1_ecc;
    float* c0    = graph ? g_c0_err    : g_c0_ecc;

    for (int idx = threadIdx.x; idx < 25 * 64; idx += blockDim.x) {
        const int tp = idx >> 6;
        const int g  = idx & 63;
        float s0 = 0.f, s1 = 0.f;
        for (int c = 0; c < 32; c++) {
            #pragma unroll
            for (int k = 0; k < 3; k++) {
                const int tt = tp - k + 1;
                if (tt >= 0 && tt < 25) {
                    const float w = wt[c * 3 + k];
                    s0 += w * W0[(c * 25 + tt) * 64 + g];
                    s1 += w * W1[(c * 25 + tt) * 64 + g];
                }
            }
        }
        Weff0[idx] = s0;
        Weff1[idx] = s1;
    }

    for (int g = threadIdx.x; g < 64; g += blockDim.x) {
        float s = 0.f;
        for (int c = 0; c < 32; c++) {
            float a0 = 0.f, a1 = 0.f;
            for (int tt = 0; tt < 25; tt++) {
                a0 += W0[(c * 25 + tt) * 64 + g];
                a1 += W1[(c * 25 + tt) * 64 + g];
            }
            s += bt[c] * (a0 - a1);
        }
        c0[g] = s + bb[g];
    }
}

// ---------------------------------------------------------------------------
// P2: fold ChebConv + per-graph projection Wp into one matrix R per graph.
//   R[u*25+t'][h] = sum_g Weff0[t'][g]*Wp[(u*64+g)*256+h]
//                 - 0.5*sum_g Weff1[t'][g]*(Wp[(up*64+g)*256+h] + Wp[(um*64+g)*256+h])
//   bias[h] = sum_v sum_g c0[g]*Wp[(v*64+g)*256+h] + bp[h]
// blocks 0..399: ecc rows; 400..699: err rows; 700/701: biases.
// ---------------------------------------------------------------------------
__global__ void precompute_R(
    const float* __restrict__ Wp_ecc, const float* __restrict__ bp_ecc,
    const float* __restrict__ Wp_err, const float* __restrict__ bp_err)
{
    const int h   = threadIdx.x;   // 0..255
    const int blk = blockIdx.x;

    if (blk < 700) {
        const int graph = (blk >= 400);
        const int row   = graph ? blk - 400 : blk;
        const int V     = graph ? 12 : 16;
        const float* Wp     = graph ? Wp_err      : Wp_ecc;
        const float* Weff0  = graph ? g_Weff0_err : g_Weff0_ecc;
        const float* Weff1  = graph ? g_Weff1_err : g_Weff1_ecc;
        float* R            = graph ? g_R_err     : g_R_ecc;

        const int u  = row / 25;
        const int tp = row % 25;
        const int up = (u + 1) % V;
        const int um = (u + V - 1) % V;

        float acc = 0.f;
        for (int g = 0; g < 64; g++) {
            const float w0 = Weff0[tp * 64 + g];
            const float w1 = Weff1[tp * 64 + g];
            acc = fmaf(w0, Wp[(u  * 64 + g) * 256 + h], acc);
            acc = fmaf(-0.5f * w1,
                       Wp[(up * 64 + g) * 256 + h] + Wp[(um * 64 + g) * 256 + h],
                       acc);
        }
        R[row * 256 + h] = acc;
    } else {
        const int graph = blk - 700;
        const int V     = graph ? 12 : 16;
        const float* Wp = graph ? Wp_err   : Wp_ecc;
        const float* bp = graph ? bp_err   : bp_ecc;
        const float* c0 = graph ? g_c0_err : g_c0_ecc;
        float* bias     = graph ? g_bias_err : g_bias_ecc;

        float acc = bp[h];
        for (int g = 0; g < 64; g++) {
            const float cs = c0[g];
            for (int v = 0; v < V; v++)
                acc = fmaf(cs, Wp[(v * 64 + g) * 256 + h], acc);
        }
        bias[h] = acc;
    }
}

// ---------------------------------------------------------------------------
// P3: main fused kernel. 16 batch rows per block, 256 threads (one per h).
//   ecc_g = x_ecc[400] @ R_ecc + bias_ecc
//   err_g = x_err[300] @ R_err + bias_err
//   attn  = sigmoid(tanh(ecc_g+err_g) @ Wa + ba)      (block reduction)
//   fused = attn*ecc_g + (1-attn)*err_g
//   ehr_p = relu(ehr @ We + be)
//   out   = sigmoid(relu([fused, ehr_p]) @ Wf2 + bf2) (block reduction)
// ---------------------------------------------------------------------------
__global__ __launch_bounds__(256) void main_kernel(
    const float* __restrict__ ecc, const float* __restrict__ err,
    const float* __restrict__ ehr,
    const float* __restrict__ We, const float* __restrict__ be,
    const float* __restrict__ Wa, const float* __restrict__ ba,
    const float* __restrict__ Wf2, const float* __restrict__ bf2,
    float* __restrict__ out)
{
    __shared__ float xs_ecc[16 * 400];   // later aliased as red[16*256]
    __shared__ float xs_err[16 * 300];   // later aliased as ehrp[16*64]
    __shared__ float xs_ehr[16 * 64];
    __shared__ float attn_s[16];

    const int t  = threadIdx.x;
    const int b0 = blockIdx.x * 16;

    // --- load batch tile (all contiguous row-major) ---
    for (int i = t; i < 16 * 400; i += 256) xs_ecc[i] = ecc[b0 * 400 + i];
    for (int i = t; i < 16 * 300; i += 256) xs_err[i] = err[b0 * 300 + i];
    for (int i = t; i < 16 * 64;  i += 256) xs_ehr[i] = ehr[b0 * 64 + i];
    __syncthreads();

    // --- the two fused GEMMs: thread t owns output column h = t ---
    float acc_e[16], acc_r[16];
    {
        const float bbe = g_bias_ecc[t];
        const float bbr = g_bias_err[t];
        #pragma unroll
        for (int r = 0; r < 16; r++) { acc_e[r] = bbe; acc_r[r] = bbr; }
    }

    #pragma unroll 4
    for (int k = 0; k < 400; k++) {
        const float w = g_R_ecc[k * 256 + t];
        #pragma unroll
        for (int r = 0; r < 16; r++)
            acc_e[r] = fmaf(xs_ecc[r * 400 + k], w, acc_e[r]);
    }
    #pragma unroll 4
    for (int k = 0; k < 300; k++) {
        const float w = g_R_err[k * 256 + t];
        #pragma unroll
        for (int r = 0; r < 16; r++)
            acc_r[r] = fmaf(xs_err[r * 300 + k], w, acc_r[r]);
    }
    __syncthreads();   // done reading xs_ecc / xs_err — safe to alias below

    // --- ehr MLP: thread group tg=t/64 handles rows tg*4..tg*4+3, col j=t%64 ---
    float* ehrp = xs_err;   // alias [16*64]
    {
        const int tg = t >> 6, j = t & 63;
        const float bj = be[j];
        #pragma unroll
        for (int rr = 0; rr < 4; rr++) {
            const int r = tg * 4 + rr;
            float a = bj;
            #pragma unroll 8
            for (int k = 0; k < 64; k++)
                a = fmaf(xs_ehr[r * 64 + k], We[k * 64 + j], a);
            ehrp[r * 64 + j] = fmaxf(a, 0.f);
        }
    }

    // --- attention: s[r] = sum_h tanh(e+r)*Wa[h];  attn = sigmoid(s+ba) ---
    float* red = xs_ecc;    // alias [16*256]
    const float wa = Wa[t];
    #pragma unroll
    for (int r = 0; r < 16; r++)
        red[r * 256 + t] = tanhf(acc_e[r] + acc_r[r]) * wa;
    __syncthreads();

    const int wid = t >> 5, lane = t & 31;
    #pragma unroll
    for (int rr = 0; rr < 2; rr++) {
        const int r = wid * 2 + rr;
        float s = 0.f;
        #pragma unroll
        for (int c = 0; c < 8; c++) s += red[r * 256 + c * 32 + lane];
        #pragma unroll
        for (int off = 16; off > 0; off >>= 1)
            s += __shfl_xor_sync(0xffffffffu, s, off);
        if (lane == 0) attn_s[r] = 1.f / (1.f + __expf(-(s + ba[0])));
    }
    __syncthreads();

    // --- final: out = sigmoid(relu(fused)@Wf2[:256] + ehrp@Wf2[256:] + bf2) ---
    const float wf   = Wf2[t];
    const float wf2e = (t < 64) ? Wf2[256 + t] : 0.f;
    #pragma unroll
    for (int r = 0; r < 16; r++) {
        const float a = attn_s[r];
        const float fused = a * acc_e[r] + (1.f - a) * acc_r[r];
        float v = fmaxf(fused, 0.f) * wf;
        if (t < 64) v = fmaf(ehrp[r * 64 + t], wf2e, v);
        red[r * 256 + t] = v;
    }
    __syncthreads();

    #pragma unroll
    for (int rr = 0; rr < 2; rr++) {
        const int r = wid * 2 + rr;
        float s = 0.f;
        #pragma unroll
        for (int c = 0; c < 8; c++) s += red[r * 256 + c * 32 + lane];
        #pragma unroll
        for (int off = 16; off > 0; off >>= 1)
            s += __shfl_xor_sync(0xffffffffu, s, off);
        if (lane == 0) out[b0 + r] = 1.f / (1.f + __expf(-(s + bf2[0])));
    }
}

// ---------------------------------------------------------------------------
// kernel_launch — inputs in metadata order:
//  0 ecc[8192,16,25] 1 err[8192,12,25] 2 ehr[8192,64]
//  3 wt_ecc[32,1,3] 4 bt_ecc[32] 5 wt_err 6 bt_err
//  7 W0_ecc[800,64] 8 W1_ecc 9 b_ecc[64] 10 W0_err 11 W1_err 12 b_err
// 13 Wp_ecc[1024,256] 14 bp_ecc[256] 15 Wp_err[768,256] 16 bp_err
// 17 Wa[256] 18 ba[1] 19 We[64,64] 20 be[64] 21 Wf2[320] 22 bf2[1]
// ---------------------------------------------------------------------------
extern "C" void kernel_launch(void* const* d_in, const int* in_sizes, int n_in,
                              void* d_out, int out_size) {
    const float* ecc    = (const float*)d_in[0];
    const float* err    = (const float*)d_in[1];
    const float* ehr    = (const float*)d_in[2];
    const float* wt_ecc = (const float*)d_in[3];
    const float* bt_ecc = (const float*)d_in[4];
    const float* wt_err = (const float*)d_in[5];
    const float* bt_err = (const float*)d_in[6];
    const float* W0_ecc = (const float*)d_in[7];
    const float* W1_ecc = (const float*)d_in[8];
    const float* b_ecc  = (const float*)d_in[9];
    const float* W0_err = (const float*)d_in[10];
    const float* W1_err = (const float*)d_in[11];
    const float* b_err  = (const float*)d_in[12];
    const float* Wp_ecc = (const float*)d_in[13];
    const float* bp_ecc = (const float*)d_in[14];
    const float* Wp_err = (const float*)d_in[15];
    const float* bp_err = (const float*)d_in[16];
    const float* Wa     = (const float*)d_in[17];
    const float* ba     = (const float*)d_in[18];
    const float* We     = (const float*)d_in[19];
    const float* be     = (const float*)d_in[20];
    const float* Wf2    = (const float*)d_in[21];
    const float* bf2    = (const float*)d_in[22];

    precompute_weff<<<2, 256>>>(wt_ecc, bt_ecc, wt_err, bt_err,
                                W0_ecc, W1_ecc, b_ecc, W0_err, W1_err, b_err);
    precompute_R<<<702, 256>>>(Wp_ecc, bp_ecc, Wp_err, bp_err);
    main_kernel<<<8192 / 16, 256>>>(ecc, err, ehr, We, be, Wa, ba, Wf2, bf2,
                                    (float*)d_out);
}

// round 2
// speedup vs baseline: 1.4061x; 1.4061x over previous
#include <cuda_runtime.h>
#include <math.h>

// ---------------------------------------------------------------------------
// Precomputed effective weights (device globals; rebuilt every launch)
// ---------------------------------------------------------------------------
__device__ float g_Weff0_ecc[25 * 64];
__device__ float g_Weff1_ecc[25 * 64];
__device__ float g_c0_ecc[64];
__device__ float g_Weff0_err[25 * 64];
__device__ float g_Weff1_err[25 * 64];
__device__ float g_c0_err[64];

__device__ float g_R_ecc[400 * 256];   // [V_ECC*25, 256]
__device__ float g_R_err[300 * 256];   // [V_ERR*25, 256]
__device__ float g_bias_ecc[256];
__device__ float g_bias_err[256];

// ---------------------------------------------------------------------------
// P1: fold temporal Conv1d (k=3, SAME, cross-correlation) into ChebConv W0/W1.
// grid = (2 graphs, 8 chunks). Chunks 0..6: Weff elements. Chunk 7: c0 vector
// (parallelized over 256 threads with an smem reduction — previously this was
// 64 threads doing 3200 serial LDGs and cost ~90us).
// ---------------------------------------------------------------------------
__global__ void precompute_weff(
    const float* __restrict__ wt_ecc, const float* __restrict__ bt_ecc,
    const float* __restrict__ wt_err, const float* __restrict__ bt_err,
    const float* __restrict__ W0_ecc, const float* __restrict__ W1_ecc,
    const float* __restrict__ b_ecc,
    const float* __restrict__ W0_err, const float* __restrict__ W1_err,
    const float* __restrict__ b_err)
{
    const int graph = blockIdx.x;  // 0 = ecc, 1 = err
    const float* wt = graph ? wt_err : wt_ecc;
    const float* bt = graph ? bt_err : bt_ecc;
    const float* W0 = graph ? W0_err : W0_ecc;
    const float* W1 = graph ? W1_err : W1_ecc;
    const float* bb = graph ? b_err  : b_ecc;
    float* Weff0 = graph ? g_Weff0_err : g_Weff0_ecc;
    float* Weff1 = graph ? g_Weff1_err : g_Weff1_ecc;
    float* c0    = graph ? g_c0_err    : g_c0_ecc;

    const int t = threadIdx.x;

    if (blockIdx.y < 7) {
        const int idx = blockIdx.y * 256 + t;
        if (idx < 25 * 64) {
            const int tp = idx >> 6;
            const int g  = idx & 63;
            float s0 = 0.f, s1 = 0.f;
            #pragma unroll 4
            for (int c = 0; c < 32; c++) {
                #pragma unroll
                for (int k = 0; k < 3; k++) {
                    const int tt = tp - k + 1;
                    if (tt >= 0 && tt < 25) {
                        const float w = wt[c * 3 + k];
                        s0 += w * W0[(c * 25 + tt) * 64 + g];
                        s1 += w * W1[(c * 25 + tt) * 64 + g];
                    }
                }
            }
            Weff0[idx] = s0;
            Weff1[idx] = s1;
        }
    } else {
        // c0[g] = sum_c bt[c] * (colsum_t (W0-W1))[c][g] + b[g]
        __shared__ float part[256];
        const int g  = t & 63;
        const int cc = t >> 6;            // 4 chunks of 8 channels
        float s = 0.f;
        for (int c = cc * 8; c < cc * 8 + 8; c++) {
            float a = 0.f;
            #pragma unroll
            for (int tt = 0; tt < 25; tt++)
                a += W0[(c * 25 + tt) * 64 + g] - W1[(c * 25 + tt) * 64 + g];
            s += bt[c] * a;
        }
        part[t] = s;
        __syncthreads();
        if (t < 64)
            c0[g] = part[g] + part[64 + g] + part[128 + g] + part[192 + g] + bb[g];
    }
}

// ---------------------------------------------------------------------------
// P2: fold ChebConv + per-graph projection Wp into one matrix R per graph.
// blocks 0..399: ecc rows; 400..699: err rows; 700/701: biases.
// ---------------------------------------------------------------------------
__global__ void precompute_R(
    const float* __restrict__ Wp_ecc, const float* __restrict__ bp_ecc,
    const float* __restrict__ Wp_err, const float* __restrict__ bp_err)
{
    const int h   = threadIdx.x;   // 0..255
    const int blk = blockIdx.x;

    if (blk < 700) {
        const int graph = (blk >= 400);
        const int row   = graph ? blk - 400 : blk;
        const int V     = graph ? 12 : 16;
        const float* Wp     = graph ? Wp_err      : Wp_ecc;
        const float* Weff0  = graph ? g_Weff0_err : g_Weff0_ecc;
        const float* Weff1  = graph ? g_Weff1_err : g_Weff1_ecc;
        float* R            = graph ? g_R_err     : g_R_ecc;

        const int u  = row / 25;
        const int tp = row % 25;
        const int up = (u + 1) % V;
        const int um = (u + V - 1) % V;

        // stage the two Weff rows in smem (128 floats)
        __shared__ float w0s[64], w1s[64];
        if (h < 64)       w0s[h]      = Weff0[tp * 64 + h];
        else if (h < 128) w1s[h - 64] = Weff1[tp * 64 + (h - 64)];
        __syncthreads();

        float acc = 0.f;
        #pragma unroll 4
        for (int g = 0; g < 64; g++) {
            acc = fmaf(w0s[g], Wp[(u  * 64 + g) * 256 + h], acc);
            acc = fmaf(-0.5f * w1s[g],
                       Wp[(up * 64 + g) * 256 + h] + Wp[(um * 64 + g) * 256 + h],
                       acc);
        }
        R[row * 256 + h] = acc;
    } else {
        const int graph = blk - 700;
        const int V     = graph ? 12 : 16;
        const float* Wp = graph ? Wp_err   : Wp_ecc;
        const float* bp = graph ? bp_err   : bp_ecc;
        const float* c0 = graph ? g_c0_err : g_c0_ecc;
        float* bias     = graph ? g_bias_err : g_bias_ecc;

        float acc = bp[h];
        for (int g = 0; g < 64; g++) {
            const float cs = c0[g];
            #pragma unroll 4
            for (int v = 0; v < V; v++)
                acc = fmaf(cs, Wp[(v * 64 + g) * 256 + h], acc);
        }
        bias[h] = acc;
    }
}

// ---------------------------------------------------------------------------
// P3: main fused kernel, f32x2-packed.
// 16 batch rows per block, 256 threads (one output column h = t each).
// Batch tile is stored TRANSPOSED in smem (xsT[k][r], row stride 20 floats)
// so that row-pairs are contiguous 64-bit operands for fma.rn.f32x2.
// The 32KB xsT buffer is reused: ecc phase -> err phase -> (red/ehrp aliases).
// ---------------------------------------------------------------------------
#define FMA2(acc, x, w) \
    asm("fma.rn.f32x2 %0, %1, %2, %0;" : "+l"(acc) : "l"(x), "l"(w))

__global__ __launch_bounds__(256) void main_kernel(
    const float* __restrict__ ecc, const float* __restrict__ err,
    const float* __restrict__ ehr,
    const float* __restrict__ We, const float* __restrict__ be,
    const float* __restrict__ Wa, const float* __restrict__ ba,
    const float* __restrict__ Wf2, const float* __restrict__ bf2,
    float* __restrict__ out)
{
    __shared__ __align__(16) float xsT[400 * 20];   // 32000 B; aliased later
    __shared__ float xs_ehr[16 * 64];
    __shared__ float attn_s[16];

    const int t  = threadIdx.x;
    const int b0 = blockIdx.x * 16;

    // ---- phase 0: load ehr + ecc^T ----
    for (int i = t; i < 16 * 64; i += 256) xs_ehr[i] = ehr[b0 * 64 + i];
    for (int i = t; i < 16 * 400; i += 256) {
        const int r = i / 400, k = i - r * 400;
        xsT[k * 20 + r] = ecc[b0 * 400 + i];
    }
    __syncthreads();

    // ---- ecc GEMM: acc pairs over rows (2j, 2j+1), column h = t ----
    unsigned long long accE[8], accR[8];
    {
        const float bb = g_bias_ecc[t];
        unsigned long long b2;
        asm("mov.b64 %0, {%1, %1};" : "=l"(b2) : "f"(bb));
        #pragma unroll
        for (int j = 0; j < 8; j++) accE[j] = b2;
    }
    {
        const float* __restrict__ Rc = g_R_ecc + t;
        #pragma unroll 2
        for (int k = 0; k < 400; k++) {
            const float wk = Rc[k * 256];
            unsigned long long w2;
            asm("mov.b64 %0, {%1, %1};" : "=l"(w2) : "f"(wk));
            const ulonglong2* xp = (const ulonglong2*)(xsT + k * 20);
            const ulonglong2 p0 = xp[0], p1 = xp[1], p2 = xp[2], p3 = xp[3];
            FMA2(accE[0], p0.x, w2); FMA2(accE[1], p0.y, w2);
            FMA2(accE[2], p1.x, w2); FMA2(accE[3], p1.y, w2);
            FMA2(accE[4], p2.x, w2); FMA2(accE[5], p2.y, w2);
            FMA2(accE[6], p3.x, w2); FMA2(accE[7], p3.y, w2);
        }
    }
    __syncthreads();   // everyone done reading ecc tile

    // ---- load err^T into the same buffer ----
    for (int i = t; i < 16 * 300; i += 256) {
        const int r = i / 300, k = i - r * 300;
        xsT[k * 20 + r] = err[b0 * 300 + i];
    }
    {
        const float bb = g_bias_err[t];
        unsigned long long b2;
        asm("mov.b64 %0, {%1, %1};" : "=l"(b2) : "f"(bb));
        #pragma unroll
        for (int j = 0; j < 8; j++) accR[j] = b2;
    }
    __syncthreads();

    // ---- err GEMM ----
    {
        const float* __restrict__ Rc = g_R_err + t;
        #pragma unroll 2
        for (int k = 0; k < 300; k++) {
            const float wk = Rc[k * 256];
            unsigned long long w2;
            asm("mov.b64 %0, {%1, %1};" : "=l"(w2) : "f"(wk));
            const ulonglong2* xp = (const ulonglong2*)(xsT + k * 20);
            const ulonglong2 p0 = xp[0], p1 = xp[1], p2 = xp[2], p3 = xp[3];
            FMA2(accR[0], p0.x, w2); FMA2(accR[1], p0.y, w2);
            FMA2(accR[2], p1.x, w2); FMA2(accR[3], p1.y, w2);
            FMA2(accR[4], p2.x, w2); FMA2(accR[5], p2.y, w2);
            FMA2(accR[6], p3.x, w2); FMA2(accR[7], p3.y, w2);
        }
    }
    __syncthreads();   // done reading err tile -> safe to alias xsT

    // unpack accumulators
    float acc_e[16], acc_r[16];
    #pragma unroll
    for (int j = 0; j < 8; j++) {
        float lo, hi;
        asm("mov.b64 {%0, %1}, %2;" : "=f"(lo), "=f"(hi) : "l"(accE[j]));
        acc_e[2 * j] = lo; acc_e[2 * j + 1] = hi;
        asm("mov.b64 {%0, %1}, %2;" : "=f"(lo), "=f"(hi) : "l"(accR[j]));
        acc_r[2 * j] = lo; acc_r[2 * j + 1] = hi;
    }

    // ---- aliases into xsT (8000 floats): red[0..4096), ehrp[4096..5120) ----
    float* red  = xsT;
    float* ehrp = xsT + 4096;

    // ---- ehr MLP: group tg=t/64 handles rows tg*4..+3, col j=t%64 ----
    {
        const int tg = t >> 6, j = t & 63;
        const float bj = be[j];
        #pragma unroll
        for (int rr = 0; rr < 4; rr++) {
            const int r = tg * 4 + rr;
            float a = bj;
            #pragma unroll 8
            for (int k = 0; k < 64; k++)
                a = fmaf(xs_ehr[r * 64 + k], We[k * 64 + j], a);
            ehrp[r * 64 + j] = fmaxf(a, 0.f);
        }
    }

    // ---- attention: attn = sigmoid(sum_h tanh(e+r)*Wa[h] + ba) ----
    const float wa = Wa[t];
    #pragma unroll
    for (int r = 0; r < 16; r++)
        red[r * 256 + t] = tanhf(acc_e[r] + acc_r[r]) * wa;
    __syncthreads();

    const int wid = t >> 5, lane = t & 31;
    #pragma unroll
    for (int rr = 0; rr < 2; rr++) {
        const int r = wid * 2 + rr;
        float s = 0.f;
        #pragma unroll
        for (int c = 0; c < 8; c++) s += red[r * 256 + c * 32 + lane];
        #pragma unroll
        for (int off = 16; off > 0; off >>= 1)
            s += __shfl_xor_sync(0xffffffffu, s, off);
        if (lane == 0) attn_s[r] = 1.f / (1.f + __expf(-(s + ba[0])));
    }
    __syncthreads();

    // ---- final: sigmoid(relu(fused)@Wf2[:256] + ehrp@Wf2[256:] + bf2) ----
    const float wf   = Wf2[t];
    const float wf2e = (t < 64) ? Wf2[256 + t] : 0.f;
    #pragma unroll
    for (int r = 0; r < 16; r++) {
        const float a = attn_s[r];
        const float fused = a * acc_e[r] + (1.f - a) * acc_r[r];
        float v = fmaxf(fused, 0.f) * wf;
        if (t < 64) v = fmaf(ehrp[r * 64 + t], wf2e, v);
        red[r * 256 + t] = v;
    }
    __syncthreads();

    #pragma unroll
    for (int rr = 0; rr < 2; rr++) {
        const int r = wid * 2 + rr;
        float s = 0.f;
        #pragma unroll
        for (int c = 0; c < 8; c++) s += red[r * 256 + c * 32 + lane];
        #pragma unroll
        for (int off = 16; off > 0; off >>= 1)
            s += __shfl_xor_sync(0xffffffffu, s, off);
        if (lane == 0) out[b0 + r] = 1.f / (1.f + __expf(-(s + bf2[0])));
    }
}

// ---------------------------------------------------------------------------
// kernel_launch — inputs in metadata order (see round-0 comment)
// ---------------------------------------------------------------------------
extern "C" void kernel_launch(void* const* d_in, const int* in_sizes, int n_in,
                              void* d_out, int out_size) {
    const float* ecc    = (const float*)d_in[0];
    const float* err    = (const float*)d_in[1];
    const float* ehr    = (const float*)d_in[2];
    const float* wt_ecc = (const float*)d_in[3];
    const float* bt_ecc = (const float*)d_in[4];
    const float* wt_err = (const float*)d_in[5];
    const float* bt_err = (const float*)d_in[6];
    const float* W0_ecc = (const float*)d_in[7];
    const float* W1_ecc = (const float*)d_in[8];
    const float* b_ecc  = (const float*)d_in[9];
    const float* W0_err = (const float*)d_in[10];
    const float* W1_err = (const float*)d_in[11];
    const float* b_err  = (const float*)d_in[12];
    const float* Wp_ecc = (const float*)d_in[13];
    const float* bp_ecc = (const float*)d_in[14];
    const float* Wp_err = (const float*)d_in[15];
    const float* bp_err = (const float*)d_in[16];
    const float* Wa     = (const float*)d_in[17];
    const float* ba     = (const float*)d_in[18];
    const float* We     = (const float*)d_in[19];
    const float* be     = (const float*)d_in[20];
    const float* Wf2    = (const float*)d_in[21];
    const float* bf2    = (const float*)d_in[22];

    dim3 g1(2, 8);
    precompute_weff<<<g1, 256>>>(wt_ecc, bt_ecc, wt_err, bt_err,
                                 W0_ecc, W1_ecc, b_ecc, W0_err, W1_err, b_err);
    precompute_R<<<702, 256>>>(Wp_ecc, bp_ecc, Wp_err, bp_err);
    main_kernel<<<8192 / 16, 256>>>(ecc, err, ehr, We, be, Wa, ba, Wf2, bf2,
                                    (float*)d_out);
}

// round 3
// speedup vs baseline: 1.9995x; 1.4220x over previous
#include <cuda_runtime.h>
#include <math.h>

// ---------------------------------------------------------------------------
// Device globals (rebuilt every launch)
// ---------------------------------------------------------------------------
__device__ float g_Weff0_ecc[25 * 64];
__device__ float g_Weff1_ecc[25 * 64];
__device__ float g_c0_ecc[64];
__device__ float g_Weff0_err[25 * 64];
__device__ float g_Weff1_err[25 * 64];
__device__ float g_c0_err[64];

__device__ float g_R_ecc[400 * 256];     // [V_ECC*25, 256]
__device__ float g_R_err[300 * 256];     // [V_ERR*25, 256]
__device__ float g_bias_part[28 * 256];  // rows 0..15: ecc u; 16..27: err u

#define FMA2(acc, x, w) \
    asm("fma.rn.f32x2 %0, %1, %2, %0;" : "+l"(acc) : "l"(x), "l"(w))
#define PACK2(d, f) \
    asm("mov.b64 %0, {%1, %1};" : "=l"(d) : "f"(f))
#define UNPACK2(lo, hi, d) \
    asm("mov.b64 {%0, %1}, %2;" : "=f"(lo), "=f"(hi) : "l"(d))

// ---------------------------------------------------------------------------
// P1: fold Conv1d (k=3, SAME) into Cheb weights. grid=(2 graphs, 26).
// y = 0..24: one Weff row t' per block (256 thr: g = t&63, 8-ch chunk = t>>6).
// y = 25:    c0[g] = sum_c bt[c] * colsum_t (W0-W1)[c][g] + b[g].
// ---------------------------------------------------------------------------
__global__ void precompute_weff(
    const float* __restrict__ wt_ecc, const float* __restrict__ bt_ecc,
    const float* __restrict__ wt_err, const float* __restrict__ bt_err,
    const float* __restrict__ W0_ecc, const float* __restrict__ W1_ecc,
    const float* __restrict__ b_ecc,
    const float* __restrict__ W0_err, const float* __restrict__ W1_err,
    const float* __restrict__ b_err)
{
    const int graph = blockIdx.x;
    const float* wt = graph ? wt_err : wt_ecc;
    const float* bt = graph ? bt_err : bt_ecc;
    const float* W0 = graph ? W0_err : W0_ecc;
    const float* W1 = graph ? W1_err : W1_ecc;
    const float* bb = graph ? b_err  : b_ecc;
    float* Weff0 = graph ? g_Weff0_err : g_Weff0_ecc;
    float* Weff1 = graph ? g_Weff1_err : g_Weff1_ecc;
    float* c0    = graph ? g_c0_err    : g_c0_ecc;

    const int t = threadIdx.x;
    const int g = t & 63;
    const int cb = (t >> 6) * 8;
    __shared__ float p0[256], p1[256];

    if (blockIdx.y < 25) {
        const int tp = blockIdx.y;
        float s0 = 0.f, s1 = 0.f;
        #pragma unroll
        for (int ci = 0; ci < 8; ci++) {
            const int c = cb + ci;
            #pragma unroll
            for (int k = 0; k < 3; k++) {
                const int tt = tp - k + 1;
                if (tt >= 0 && tt < 25) {
                    const float w = wt[c * 3 + k];
                    s0 = fmaf(w, W0[(c * 25 + tt) * 64 + g], s0);
                    s1 = fmaf(w, W1[(c * 25 + tt) * 64 + g], s1);
                }
            }
        }
        p0[t] = s0; p1[t] = s1;
        __syncthreads();
        if (t < 64) {
            Weff0[tp * 64 + t] = p0[t] + p0[64 + t] + p0[128 + t] + p0[192 + t];
            Weff1[tp * 64 + t] = p1[t] + p1[64 + t] + p1[128 + t] + p1[192 + t];
        }
    } else {
        float s = 0.f;
        #pragma unroll
        for (int ci = 0; ci < 8; ci++) {
            const int c = cb + ci;
            float a = 0.f;
            #pragma unroll
            for (int tt = 0; tt < 25; tt++)
                a += W0[(c * 25 + tt) * 64 + g] - W1[(c * 25 + tt) * 64 + g];
            s = fmaf(bt[c], a, s);
        }
        p0[t] = s;
        __syncthreads();
        if (t < 64)
            c0[g] = p0[g] + p0[64 + g] + p0[128 + g] + p0[192 + g] + bb[g];
    }
}

// ---------------------------------------------------------------------------
// P2: one block per (graph, node u) — 28 blocks, 256 threads (h = t).
// All 25 t' rows of node u share the same 3 Wp row-bands (u, u+1, u-1), so
// each Wp value is loaded once per block. t'-pairs packed for f32x2.
// Also emits per-u bias partials (bias = sum_u part[u]; block u==0 adds bp).
// ---------------------------------------------------------------------------
__global__ __launch_bounds__(256) void precompute_R(
    const float* __restrict__ Wp_ecc, const float* __restrict__ bp_ecc,
    const float* __restrict__ Wp_err, const float* __restrict__ bp_err)
{
    const int h   = threadIdx.x;
    const int blk = blockIdx.x;
    const int graph = (blk >= 16);
    const int u     = graph ? blk - 16 : blk;
    const int V     = graph ? 12 : 16;
    const float* Wp    = graph ? Wp_err      : Wp_ecc;
    const float* bp    = graph ? bp_err      : bp_ecc;
    const float* Weff0 = graph ? g_Weff0_err : g_Weff0_ecc;
    const float* Weff1 = graph ? g_Weff1_err : g_Weff1_ecc;
    const float* c0g   = graph ? g_c0_err    : g_c0_ecc;
    float* R           = graph ? g_R_err     : g_R_ecc;

    __shared__ __align__(16) float w0s[64 * 28];   // g-major, padded
    __shared__ __align__(16) float w1s[64 * 28];   // holds -0.5*Weff1
    __shared__ float c0s[64];

    for (int idx = h; idx < 1600; idx += 256) {
        const int tp = idx >> 6, g = idx & 63;
        w0s[g * 28 + tp] = Weff0[idx];
        w1s[g * 28 + tp] = -0.5f * Weff1[idx];
    }
    if (h < 64) c0s[h] = c0g[h];
    __syncthreads();

    const int up = (u + 1) % V;
    const int um = (u + V - 1) % V;

    unsigned long long acc2[12];
    #pragma unroll
    for (int j = 0; j < 12; j++) acc2[j] = 0ull;
    float acc24 = 0.f;
    float pbias = (u == 0) ? bp[h] : 0.f;

    #pragma unroll 2
    for (int g = 0; g < 64; g++) {
        const float wp_u = Wp[(u  * 64 + g) * 256 + h];
        const float wp_s = Wp[(up * 64 + g) * 256 + h] +
                           Wp[(um * 64 + g) * 256 + h];
        pbias = fmaf(c0s[g], wp_u, pbias);
        unsigned long long u2, s2;
        PACK2(u2, wp_u); PACK2(s2, wp_s);
        const ulonglong2* w0p = (const ulonglong2*)(w0s + g * 28);
        const ulonglong2* w1p = (const ulonglong2*)(w1s + g * 28);
        #pragma unroll
        for (int q = 0; q < 6; q++) {
            const ulonglong2 a = w0p[q];
            const ulonglong2 b = w1p[q];
            FMA2(acc2[2 * q],     a.x, u2);
            FMA2(acc2[2 * q],     b.x, s2);
            FMA2(acc2[2 * q + 1], a.y, u2);
            FMA2(acc2[2 * q + 1], b.y, s2);
        }
        acc24 = fmaf(w0s[g * 28 + 24], wp_u, acc24);
        acc24 = fmaf(w1s[g * 28 + 24], wp_s, acc24);
    }

    #pragma unroll
    for (int j = 0; j < 12; j++) {
        float lo, hi;
        UNPACK2(lo, hi, acc2[j]);
        R[(u * 25 + 2 * j)     * 256 + h] = lo;
        R[(u * 25 + 2 * j + 1) * 256 + h] = hi;
    }
    R[(u * 25 + 24) * 256 + h] = acc24;
    g_bias_part[blk * 256 + h] = pbias;
}

// ---------------------------------------------------------------------------
// P3: main fused kernel. 16 batch rows/block, 128 threads, 2 columns/thread
// (h0 = t, h1 = t+128). Batch tile transposed in smem (xsT[k][r], stride 20)
// so row-pairs are 64-bit f32x2 operands; each LDS.128 now feeds 16 FFMA2
// (2 cols) instead of 8 -> fma pipe is the sole binding pipe.
// ---------------------------------------------------------------------------
__global__ __launch_bounds__(128) void main_kernel(
    const float* __restrict__ ecc, const float* __restrict__ err,
    const float* __restrict__ ehr,
    const float* __restrict__ We, const float* __restrict__ be,
    const float* __restrict__ Wa, const float* __restrict__ ba,
    const float* __restrict__ Wf2, const float* __restrict__ bf2,
    float* __restrict__ out)
{
    __shared__ __align__(16) float xsT[400 * 20];   // 32000 B; aliased later
    __shared__ float xs_ehr[16 * 64];
    __shared__ float attn_s[16];

    const int t  = threadIdx.x;           // 0..127
    const int b0 = blockIdx.x * 16;

    // ---- load ehr + ecc^T ----
    for (int i = t; i < 16 * 64; i += 128) xs_ehr[i] = ehr[b0 * 64 + i];
    #pragma unroll
    for (int r = 0; r < 16; r++)
        for (int k = t; k < 400; k += 128)
            xsT[k * 20 + r] = ecc[(b0 + r) * 400 + k];

    // ---- bias partial sums (2 cols each) ----
    float bbe0 = 0.f, bbe1 = 0.f, bbr0 = 0.f, bbr1 = 0.f;
    #pragma unroll
    for (int u = 0; u < 16; u++) {
        bbe0 += g_bias_part[u * 256 + t];
        bbe1 += g_bias_part[u * 256 + t + 128];
    }
    #pragma unroll
    for (int u = 0; u < 12; u++) {
        bbr0 += g_bias_part[(16 + u) * 256 + t];
        bbr1 += g_bias_part[(16 + u) * 256 + t + 128];
    }
    __syncthreads();

    unsigned long long accE0[8], accE1[8], accR0[8], accR1[8];
    {
        unsigned long long b0p, b1p;
        PACK2(b0p, bbe0); PACK2(b1p, bbe1);
        #pragma unroll
        for (int j = 0; j < 8; j++) { accE0[j] = b0p; accE1[j] = b1p; }
    }

    // ---- ecc GEMM ----
    {
        const float* __restrict__ Rc = g_R_ecc + t;
        #pragma unroll 4
        for (int k = 0; k < 400; k++) {
            const float w0 = Rc[k * 256];
            const float w1 = Rc[k * 256 + 128];
            unsigned long long w02, w12;
            PACK2(w02, w0); PACK2(w12, w1);
            const ulonglong2* xp = (const ulonglong2*)(xsT + k * 20);
            const ulonglong2 p0 = xp[0], p1 = xp[1], p2 = xp[2], p3 = xp[3];
            FMA2(accE0[0], p0.x, w02); FMA2(accE1[0], p0.x, w12);
            FMA2(accE0[1], p0.y, w02); FMA2(accE1[1], p0.y, w12);
            FMA2(accE0[2], p1.x, w02); FMA2(accE1[2], p1.x, w12);
            FMA2(accE0[3], p1.y, w02); FMA2(accE1[3], p1.y, w12);
            FMA2(accE0[4], p2.x, w02); FMA2(accE1[4], p2.x, w12);
            FMA2(accE0[5], p2.y, w02); FMA2(accE1[5], p2.y, w12);
            FMA2(accE0[6], p3.x, w02); FMA2(accE1[6], p3.x, w12);
            FMA2(accE0[7], p3.y, w02); FMA2(accE1[7], p3.y, w12);
        }
    }
    __syncthreads();   // everyone done reading ecc tile

    // ---- load err^T into same buffer ----
    #pragma unroll
    for (int r = 0; r < 16; r++)
        for (int k = t; k < 300; k += 128)
            xsT[k * 20 + r] = err[(b0 + r) * 300 + k];
    {
        unsigned long long b0p, b1p;
        PACK2(b0p, bbr0); PACK2(b1p, bbr1);
        #pragma unroll
        for (int j = 0; j < 8; j++) { accR0[j] = b0p; accR1[j] = b1p; }
    }
    __syncthreads();

    // ---- err GEMM ----
    {
        const float* __restrict__ Rc = g_R_err + t;
        #pragma unroll 4
        for (int k = 0; k < 300; k++) {
            const float w0 = Rc[k * 256];
            const float w1 = Rc[k * 256 + 128];
            unsigned long long w02, w12;
            PACK2(w02, w0); PACK2(w12, w1);
            const ulonglong2* xp = (const ulonglong2*)(xsT + k * 20);
            const ulonglong2 p0 = xp[0], p1 = xp[1], p2 = xp[2], p3 = xp[3];
            FMA2(accR0[0], p0.x, w02); FMA2(accR1[0], p0.x, w12);
            FMA2(accR0[1], p0.y, w02); FMA2(accR1[1], p0.y, w12);
            FMA2(accR0[2], p1.x, w02); FMA2(accR1[2], p1.x, w12);
            FMA2(accR0[3], p1.y, w02); FMA2(accR1[3], p1.y, w12);
            FMA2(accR0[4], p2.x, w02); FMA2(accR1[4], p2.x, w12);
            FMA2(accR0[5], p2.y, w02); FMA2(accR1[5], p2.y, w12);
            FMA2(accR0[6], p3.x, w02); FMA2(accR1[6], p3.x, w12);
            FMA2(accR0[7], p3.y, w02); FMA2(accR1[7], p3.y, w12);
        }
    }
    __syncthreads();   // done reading err tile -> safe to alias xsT

    // unpack accumulators: rows 0..15 for cols h0=t, h1=t+128
    float e0[16], e1[16], r0[16], r1[16];
    #pragma unroll
    for (int j = 0; j < 8; j++) {
        UNPACK2(e0[2 * j], e0[2 * j + 1], accE0[j]);
        UNPACK2(e1[2 * j], e1[2 * j + 1], accE1[j]);
        UNPACK2(r0[2 * j], r0[2 * j + 1], accR0[j]);
        UNPACK2(r1[2 * j], r1[2 * j + 1], accR1[j]);
    }

    float* red  = xsT;          // [16*256]
    float* ehrp = xsT + 4096;   // [16*64]

    // ---- ehr MLP: half = t/64 handles rows half*8..+7, col j = t%64 ----
    {
        const int half = t >> 6, j = t & 63;
        const float bj = be[j];
        #pragma unroll
        for (int rr = 0; rr < 8; rr++) {
            const int r = half * 8 + rr;
            float a = bj;
            #pragma unroll 8
            for (int k = 0; k < 64; k++)
                a = fmaf(xs_ehr[r * 64 + k], We[k * 64 + j], a);
            ehrp[r * 64 + j] = fmaxf(a, 0.f);
        }
    }

    // ---- attention: attn = sigmoid(sum_h tanh(e+r)*Wa[h] + ba) ----
    const float wa0 = Wa[t], wa1 = Wa[t + 128];
    #pragma unroll
    for (int r = 0; r < 16; r++) {
        red[r * 256 + t]       = tanhf(e0[r] + r0[r]) * wa0;
        red[r * 256 + t + 128] = tanhf(e1[r] + r1[r]) * wa1;
    }
    __syncthreads();

    const int wid = t >> 5, lane = t & 31;
    #pragma unroll
    for (int rr = 0; rr < 4; rr++) {
        const int r = wid * 4 + rr;
        float s = 0.f;
        #pragma unroll
        for (int c = 0; c < 8; c++) s += red[r * 256 + c * 32 + lane];
        #pragma unroll
        for (int off = 16; off > 0; off >>= 1)
            s += __shfl_xor_sync(0xffffffffu, s, off);
        if (lane == 0) attn_s[r] = 1.f / (1.f + __expf(-(s + ba[0])));
    }
    __syncthreads();

    // ---- final: sigmoid(relu(fused)@Wf2[:256] + ehrp@Wf2[256:] + bf2) ----
    const float wf0  = Wf2[t];
    const float wf1  = Wf2[t + 128];
    const float wf2e = (t < 64) ? Wf2[256 + t] : 0.f;
    #pragma unroll
    for (int r = 0; r < 16; r++) {
        const float a = attn_s[r];
        float v0 = fmaxf(a * e0[r] + (1.f - a) * r0[r], 0.f) * wf0;
        float v1 = fmaxf(a * e1[r] + (1.f - a) * r1[r], 0.f) * wf1;
        if (t < 64) v0 = fmaf(ehrp[r * 64 + t], wf2e, v0);
        red[r * 256 + t]       = v0;
        red[r * 256 + t + 128] = v1;
    }
    __syncthreads();

    #pragma unroll
    for (int rr = 0; rr < 4; rr++) {
        const int r = wid * 4 + rr;
        float s = 0.f;
        #pragma unroll
        for (int c = 0; c < 8; c++) s += red[r * 256 + c * 32 + lane];
        #pragma unroll
        for (int off = 16; off > 0; off >>= 1)
            s += __shfl_xor_sync(0xffffffffu, s, off);
        if (lane == 0) out[b0 + r] = 1.f / (1.f + __expf(-(s + bf2[0])));
    }
}

// ---------------------------------------------------------------------------
extern "C" void kernel_launch(void* const* d_in, const int* in_sizes, int n_in,
                              void* d_out, int out_size) {
    const float* ecc    = (const float*)d_in[0];
    const float* err    = (const float*)d_in[1];
    const float* ehr    = (const float*)d_in[2];
    const float* wt_ecc = (const float*)d_in[3];
    const float* bt_ecc = (const float*)d_in[4];
    const float* wt_err = (const float*)d_in[5];
    const float* bt_err = (const float*)d_in[6];
    const float* W0_ecc = (const float*)d_in[7];
    const float* W1_ecc = (const float*)d_in[8];
    const float* b_ecc  = (const float*)d_in[9];
    const float* W0_err = (const float*)d_in[10];
    const float* W1_err = (const float*)d_in[11];
    const float* b_err  = (const float*)d_in[12];
    const float* Wp_ecc = (const float*)d_in[13];
    const float* bp_ecc = (const float*)d_in[14];
    const float* Wp_err = (const float*)d_in[15];
    const float* bp_err = (const float*)d_in[16];
    const float* Wa     = (const float*)d_in[17];
    const float* ba     = (const float*)d_in[18];
    const float* We     = (const float*)d_in[19];
    const float* be     = (const float*)d_in[20];
    const float* Wf2    = (const float*)d_in[21];
    const float* bf2    = (const float*)d_in[22];

    dim3 g1(2, 26);
    precompute_weff<<<g1, 256>>>(wt_ecc, bt_ecc, wt_err, bt_err,
                                 W0_ecc, W1_ecc, b_ecc, W0_err, W1_err, b_err);
    precompute_R<<<28, 256>>>(Wp_ecc, bp_ecc, Wp_err, bp_err);
    main_kernel<<<8192 / 16, 128>>>(ecc, err, ehr, We, be, Wa, ba, Wf2, bf2,
                                    (float*)d_out);
}